// round 1
// baseline (speedup 1.0000x reference)
#include <cuda_runtime.h>

#define NIMG 8
#define HWC  4096
#define NA   9
#define NG   64
#define NC   80
#define TPB  256
#define NCELLS (NIMG * HWC)
#define NBLK   (NCELLS / TPB)   // 128 blocks

// scratch for deterministic two-stage reduction (no device allocation allowed)
__device__ float g_part[NBLK * 3];

__global__ void __launch_bounds__(TPB) yolo_main(
    const float4* __restrict__ pb,   // [N,HW,A,4] (x,y,w,h)
    const float*  __restrict__ po,   // [N,HW,A]
    const float*  __restrict__ ps,   // [N,HW,A,C]
    const float4* __restrict__ gb,   // [N,G,4] xyxy
    const int*    __restrict__ gl)   // [N,G]
{
    __shared__ float sgx1[NG], sgy1[NG], sgx2[NG], sgy2[NG], sga[NG];
    __shared__ int   sgl[NG];

    const int cell = blockIdx.x * TPB + threadIdx.x;   // = n*HW + hw
    const int n = cell / HWC;

    if (threadIdx.x < NG) {
        float4 g = gb[n * NG + threadIdx.x];
        sgx1[threadIdx.x] = g.x;
        sgy1[threadIdx.x] = g.y;
        sgx2[threadIdx.x] = g.z;
        sgy2[threadIdx.x] = g.w;
        sga[threadIdx.x]  = (g.z - g.x) * (g.w - g.y);
        sgl[threadIdx.x]  = gl[n * NG + threadIdx.x];
    }
    __syncthreads();

    // Load the 9 anchor boxes for this cell, convert xywh -> xyxy
    const float4* pbp = pb + (size_t)cell * NA;
    float px1[NA], py1[NA], px2[NA], py2[NA], pa[NA], best[NA];
#pragma unroll
    for (int a = 0; a < NA; a++) {
        float4 b = pbp[a];
        px1[a] = b.x;
        py1[a] = b.y;
        px2[a] = b.x + b.z;
        py2[a] = b.y + b.w;
        pa[a]  = b.z * b.w;
        best[a] = 0.f;
    }

    // Pass 1: per-anchor max IoU over all GTs (no index tracking)
#pragma unroll 4
    for (int g = 0; g < NG; ++g) {
        const float gx1 = sgx1[g], gy1 = sgy1[g];
        const float gx2 = sgx2[g], gy2 = sgy2[g];
        const float ga  = sga[g];
#pragma unroll
        for (int a = 0; a < NA; a++) {
            float w = fminf(px2[a], gx2) - fmaxf(px1[a], gx1);
            float h = fminf(py2[a], gy2) - fmaxf(py1[a], gy1);
            w = fmaxf(w, 0.f);
            h = fmaxf(h, 0.f);
            float inter = w * h;
            float uni   = pa[a] + ga - inter;
            best[a] = fmaxf(best[a], __fdividef(inter, uni));
        }
    }

    // First-max argmax over anchors (jnp.argmax semantics: strict >)
    float bv = best[0];
    int asel = 0;
#pragma unroll
    for (int a = 1; a < NA; a++)
        if (best[a] > bv) { bv = best[a]; asel = a; }

    float obj = 0.f, bbox = 0.f, clf = 0.f;
    const float* pop = po + (size_t)cell * NA;

    if (bv > 0.f) {
        // selected anchor box (reload; L1 hit; avoids dynamic-index reg arrays)
        float4 sb = pbp[asel];
        const float sx1 = sb.x, sy1 = sb.y;
        const float sx2 = sb.x + sb.z, sy2 = sb.y + sb.w;
        const float sa  = sb.z * sb.w;

        // Pass 2: best GT for the selected anchor (first-max over g)
        float bi = -1.f;
        int   bg = 0;
#pragma unroll 4
        for (int g = 0; g < NG; ++g) {
            float w = fminf(sx2, sgx2[g]) - fmaxf(sx1, sgx1[g]);
            float h = fminf(sy2, sgy2[g]) - fmaxf(sy1, sgy1[g]);
            w = fmaxf(w, 0.f);
            h = fmaxf(h, 0.f);
            float inter = w * h;
            float iou = __fdividef(inter, sa + sga[g] - inter);
            if (iou > bi) { bi = iou; bg = g; }
        }

        // objectness loss (matched cell)
        float so = pop[asel];
        float d  = so - bi;
        obj = d * d;

        // bbox loss
        const float gx1 = sgx1[bg], gy1 = sgy1[bg];
        const float gx2 = sgx2[bg], gy2 = sgy2[bg];
        float dx = sx1 - gx1;
        float dy = sy1 - gy1;
        float dw = sqrtf(sx2) - sqrtf(gx2);
        float dh = sqrtf(sy2) - sqrtf(gy2);
        bbox = dx * dx + dy * dy + dw * dw + dh * dh;

        // classification loss: -log_softmax(scores)[label]
        const float4* sp = (const float4*)(ps + ((size_t)cell * NA + asel) * NC);
        float mx = -1e30f;
#pragma unroll
        for (int i = 0; i < NC / 4; i++) {
            float4 v = sp[i];
            mx = fmaxf(mx, fmaxf(fmaxf(v.x, v.y), fmaxf(v.z, v.w)));
        }
        float se = 0.f;
#pragma unroll
        for (int i = 0; i < NC / 4; i++) {
            float4 v = sp[i];
            se += __expf(v.x - mx) + __expf(v.y - mx) +
                  __expf(v.z - mx) + __expf(v.w - mx);
        }
        const int lab = sgl[bg];
        const float sl = ((const float*)sp)[lab];
        clf = __logf(se) + mx - sl;
    } else {
        // empty cell: 0.5 * max_a(po)^2
        float mo = pop[0];
#pragma unroll
        for (int a = 1; a < NA; a++) mo = fmaxf(mo, pop[a]);
        obj = 0.5f * mo * mo;
    }

    // Deterministic block reduction: warp shuffle + smem, fixed order
#pragma unroll
    for (int o = 16; o; o >>= 1) {
        obj  += __shfl_down_sync(0xffffffffu, obj,  o);
        bbox += __shfl_down_sync(0xffffffffu, bbox, o);
        clf  += __shfl_down_sync(0xffffffffu, clf,  o);
    }
    __shared__ float sred[3][TPB / 32];
    const int wid = threadIdx.x >> 5;
    const int lid = threadIdx.x & 31;
    if (lid == 0) {
        sred[0][wid] = obj;
        sred[1][wid] = bbox;
        sred[2][wid] = clf;
    }
    __syncthreads();
    if (threadIdx.x == 0) {
        float o = 0.f, b = 0.f, c = 0.f;
#pragma unroll
        for (int w = 0; w < TPB / 32; w++) {
            o += sred[0][w];
            b += sred[1][w];
            c += sred[2][w];
        }
        g_part[blockIdx.x * 3 + 0] = o;
        g_part[blockIdx.x * 3 + 1] = b;
        g_part[blockIdx.x * 3 + 2] = c;
    }
}

__global__ void __launch_bounds__(NBLK) yolo_reduce(float* __restrict__ out)
{
    __shared__ float s[3][NBLK];
    const int t = threadIdx.x;   // NBLK = 128 threads
    s[0][t] = g_part[t * 3 + 0];
    s[1][t] = g_part[t * 3 + 1];
    s[2][t] = g_part[t * 3 + 2];
    __syncthreads();
#pragma unroll
    for (int st = NBLK / 2; st > 0; st >>= 1) {
        if (t < st) {
            s[0][t] += s[0][t + st];
            s[1][t] += s[1][t + st];
            s[2][t] += s[2][t + st];
        }
        __syncthreads();
    }
    if (t == 0) {
        out[0] = s[0][0];
        out[1] = s[1][0];
        out[2] = s[2][0];
    }
}

extern "C" void kernel_launch(void* const* d_in, const int* in_sizes, int n_in,
                              void* d_out, int out_size)
{
    const float4* pb = (const float4*)d_in[0];  // pred_boxes  [8,4096,9,4]
    const float*  po = (const float*) d_in[1];  // pred_o      [8,4096,9]
    const float*  ps = (const float*) d_in[2];  // pred_scores [8,4096,9,80]
    const float4* gb = (const float4*)d_in[3];  // gt_boxes    [8,64,4]
    const int*    gl = (const int*)   d_in[4];  // gt_labels   [8,64]
    float* out = (float*)d_out;

    yolo_main<<<NBLK, TPB>>>(pb, po, ps, gb, gl);
    yolo_reduce<<<1, NBLK>>>(out);
}

// round 2
// speedup vs baseline: 1.1135x; 1.1135x over previous
#include <cuda_runtime.h>

#define NIMG 8
#define HWC  4096
#define NA   9
#define NG   64
#define NGH  32              // GTs per lane (pair split)
#define NC   80
#define TPB  256
#define CPB  128             // cells per block (2 threads per cell)
#define NCELLS (NIMG * HWC)
#define NBLK   (NCELLS / CPB)   // 256 blocks
#define BPI    (HWC / CPB)      // 32 blocks per image

__device__ float g_part[NBLK * 3];
__device__ int   g_count = 0;

__global__ void __launch_bounds__(TPB, 2) yolo_fused(
    const float4* __restrict__ pb,   // [N,HW,A,4] (x,y,w,h)
    const float*  __restrict__ po,   // [N,HW,A]
    const float*  __restrict__ ps,   // [N,HW,A,C]
    const float4* __restrict__ gb,   // [N,G,4] xyxy
    const int*    __restrict__ gl,   // [N,G]
    float*        __restrict__ out)
{
    __shared__ float sgx1[NG], sgy1[NG], sgx2[NG], sgy2[NG], sga[NG];
    __shared__ int   sgl[NG];

    const int tid  = threadIdx.x;
    const int half = tid & 1;                       // which GT half this lane owns
    const int cell = blockIdx.x * CPB + (tid >> 1); // 2 lanes per cell
    const int n    = blockIdx.x / BPI;

    if (tid < NG) {
        float4 g = gb[n * NG + tid];
        sgx1[tid] = g.x; sgy1[tid] = g.y;
        sgx2[tid] = g.z; sgy2[tid] = g.w;
        sga[tid]  = (g.z - g.x) * (g.w - g.y);
        sgl[tid]  = gl[n * NG + tid];
    }
    __syncthreads();

    // ---- load anchors, xywh -> xyxy ----
    const float4* pbp = pb + (size_t)cell * NA;
    float px1[NA], py1[NA], px2[NA], py2[NA], pa[NA], best[NA];
#pragma unroll
    for (int a = 0; a < NA; a++) {
        float4 b = pbp[a];
        px1[a] = b.x; py1[a] = b.y;
        px2[a] = b.x + b.z; py2[a] = b.y + b.w;
        pa[a]  = b.z * b.w;
        best[a] = 0.f;
    }

    // ---- pass 1: per-anchor max of f = inter/(pa+ga) over this lane's 32 GTs.
    // f is strictly monotone in IoU, so ordering (max/argmax/>0) is preserved.
    const int g0 = half * NGH;
#pragma unroll 4
    for (int gi = 0; gi < NGH; ++gi) {
        const int g = g0 + gi;
        const float gx1 = sgx1[g], gy1 = sgy1[g];
        const float gx2 = sgx2[g], gy2 = sgy2[g];
        const float ga  = sga[g];
#pragma unroll
        for (int a = 0; a < NA; a++) {
            float w = fminf(px2[a], gx2) - fmaxf(px1[a], gx1);
            float h = fminf(py2[a], gy2) - fmaxf(py1[a], gy1);
            w = fmaxf(w, 0.f);
            h = fmaxf(h, 0.f);
            float f = __fdividef(w * h, pa[a] + ga);
            best[a] = fmaxf(best[a], f);
        }
    }
    // combine halves (exact: max is order-insensitive)
#pragma unroll
    for (int a = 0; a < NA; a++)
        best[a] = fmaxf(best[a], __shfl_xor_sync(0xffffffffu, best[a], 1));

    // first-max argmax over anchors (strict >), identical on both lanes
    float bv = best[0];
    int asel = 0;
#pragma unroll
    for (int a = 1; a < NA; a++)
        if (best[a] > bv) { bv = best[a]; asel = a; }

    const bool sel = (bv > 0.f);
    const float* pop = po + (size_t)cell * NA;

    // ---- pass 2 (unconditional, masked later): true IoU for selected anchor ----
    float4 sb = pbp[asel];
    const float sx1 = sb.x, sy1 = sb.y;
    const float sx2 = sb.x + sb.z, sy2 = sb.y + sb.w;
    const float sa  = sb.z * sb.w;

    float bi = -1.f;
    int   bg = 0;
#pragma unroll 4
    for (int gi = 0; gi < NGH; ++gi) {
        const int g = g0 + gi;
        float w = fminf(sx2, sgx2[g]) - fmaxf(sx1, sgx1[g]);
        float h = fminf(sy2, sgy2[g]) - fmaxf(sy1, sgy1[g]);
        w = fmaxf(w, 0.f);
        h = fmaxf(h, 0.f);
        float inter = w * h;
        float iou = __fdividef(inter, sa + sga[g] - inter);
        if (iou > bi) { bi = iou; bg = g; }
    }
    // cross-lane first-max: lane1's indices are all larger, so lane1 wins only strictly
    {
        float bo = __shfl_xor_sync(0xffffffffu, bi, 1);
        int   go = __shfl_xor_sync(0xffffffffu, bg, 1);
        bool take = half ? (bo >= bi) : (bo > bi);
        if (take) { bi = bo; bg = go; }
    }

    // ---- softmax CE, split 40 classes per lane (unconditional) ----
    const float* sp = ps + ((size_t)cell * NA + asel) * NC;
    const float4* spv = (const float4*)(sp + half * (NC / 2));
    float mx = -1e30f;
    float4 v[NC / 8];
#pragma unroll
    for (int i = 0; i < NC / 8; i++) {
        v[i] = spv[i];
        mx = fmaxf(mx, fmaxf(fmaxf(v[i].x, v[i].y), fmaxf(v[i].z, v[i].w)));
    }
    mx = fmaxf(mx, __shfl_xor_sync(0xffffffffu, mx, 1));
    float se = 0.f;
#pragma unroll
    for (int i = 0; i < NC / 8; i++) {
        se += __expf(v[i].x - mx) + __expf(v[i].y - mx) +
              __expf(v[i].z - mx) + __expf(v[i].w - mx);
    }
    se += __shfl_xor_sync(0xffffffffu, se, 1);

    // ---- losses (lane0 owns the cell's contribution) ----
    float obj = 0.f, bbox = 0.f, clf = 0.f;
    if (half == 0) {
        if (sel) {
            float so = pop[asel];
            float d = so - bi;
            obj = d * d;

            const float gx1 = sgx1[bg], gy1 = sgy1[bg];
            const float gx2 = sgx2[bg], gy2 = sgy2[bg];
            float dx = sx1 - gx1;
            float dy = sy1 - gy1;
            float dw = sqrtf(sx2) - sqrtf(gx2);
            float dh = sqrtf(sy2) - sqrtf(gy2);
            bbox = dx * dx + dy * dy + dw * dw + dh * dh;

            const int lab = sgl[bg];
            const float sl = sp[lab];
            clf = __logf(se) + mx - sl;
        } else {
            float mo = pop[0];
#pragma unroll
            for (int a = 1; a < NA; a++) mo = fmaxf(mo, pop[a]);
            obj = 0.5f * mo * mo;
        }
    }

    // ---- deterministic reduction: warp -> block -> grid (last block) ----
#pragma unroll
    for (int o = 16; o; o >>= 1) {
        obj  += __shfl_down_sync(0xffffffffu, obj,  o);
        bbox += __shfl_down_sync(0xffffffffu, bbox, o);
        clf  += __shfl_down_sync(0xffffffffu, clf,  o);
    }
    __shared__ float sred[3][TPB / 32];
    const int wid = tid >> 5;
    const int lid = tid & 31;
    if (lid == 0) { sred[0][wid] = obj; sred[1][wid] = bbox; sred[2][wid] = clf; }
    __syncthreads();
    if (tid == 0) {
        float o = 0.f, b = 0.f, c = 0.f;
#pragma unroll
        for (int w = 0; w < TPB / 32; w++) { o += sred[0][w]; b += sred[1][w]; c += sred[2][w]; }
        g_part[blockIdx.x * 3 + 0] = o;
        g_part[blockIdx.x * 3 + 1] = b;
        g_part[blockIdx.x * 3 + 2] = c;
    }

    __shared__ bool isLast;
    __threadfence();
    __syncthreads();
    if (tid == 0) {
        int prev = atomicAdd(&g_count, 1);
        isLast = (prev == NBLK - 1);
    }
    __syncthreads();
    if (!isLast) return;

    // last block: deterministic tree reduce of 256 partials
    __threadfence();
    __shared__ float s[3][NBLK];
    s[0][tid] = g_part[tid * 3 + 0];
    s[1][tid] = g_part[tid * 3 + 1];
    s[2][tid] = g_part[tid * 3 + 2];
    __syncthreads();
#pragma unroll
    for (int st = NBLK / 2; st > 0; st >>= 1) {
        if (tid < st) {
            s[0][tid] += s[0][tid + st];
            s[1][tid] += s[1][tid + st];
            s[2][tid] += s[2][tid + st];
        }
        __syncthreads();
    }
    if (tid == 0) {
        out[0] = s[0][0];
        out[1] = s[1][0];
        out[2] = s[2][0];
        g_count = 0;   // reset for next graph replay
    }
}

extern "C" void kernel_launch(void* const* d_in, const int* in_sizes, int n_in,
                              void* d_out, int out_size)
{
    const float4* pb = (const float4*)d_in[0];  // pred_boxes  [8,4096,9,4]
    const float*  po = (const float*) d_in[1];  // pred_o      [8,4096,9]
    const float*  ps = (const float*) d_in[2];  // pred_scores [8,4096,9,80]
    const float4* gb = (const float4*)d_in[3];  // gt_boxes    [8,64,4]
    const int*    gl = (const int*)   d_in[4];  // gt_labels   [8,64]

    yolo_fused<<<NBLK, TPB>>>(pb, po, ps, gb, gl, (float*)d_out);
}